// round 4
// baseline (speedup 1.0000x reference)
#include <cuda_runtime.h>
#include <cuda_bf16.h>

// Problem shape (fixed by the dataset)
#define BB   256
#define NN   8192
#define SD   14
#define NPTS (BB * NN)          // 2,097,152 points
#define TPB  256
#define NBLK (NPTS / TPB)       // 8192 blocks

// Partial component index:
// 0 = trans (k 0..5), 1 = rot (k 6..12), 2 = mass (k 13),
// 3 = phys, 4 = quat, 5 = massflow
__device__ double       g_part[NBLK * 6];   // per-block double partials
__device__ unsigned int g_count;            // ticket counter (reset by last block)

// ---------------------------------------------------------------------------
// Single fused kernel: map + block partials + last-block finalize.
// ---------------------------------------------------------------------------
__global__ void __launch_bounds__(TPB)
pinn_fused_kernel(const float* __restrict__ pred,
                  const float* __restrict__ tru,
                  const float* __restrict__ t,
                  const float* __restrict__ ctrl,
                  float* __restrict__ out)
{
    const int tid = threadIdx.x;
    const int i   = blockIdx.x * TPB + tid;        // 0 .. NPTS-1
    const int n   = i & (NN - 1);                  // NN is a power of 2

    // Rows are 14 floats = 56 B; 56 % 8 == 0 -> float2-aligned everywhere.
    const float2* p2 = reinterpret_cast<const float2*>(pred);
    const float2* t2 = reinterpret_cast<const float2*>(tru);
    const int base = i * 7;
    const int pb   = base - ((n > 0)      ? 7 : 0);
    const int nb   = base + ((n < NN - 1) ? 7 : 0);

    float cur[SD], prv[SD], nxt[SD];
#pragma unroll
    for (int k = 0; k < 7; k++) { float2 v = p2[base + k]; cur[2*k] = v.x; cur[2*k+1] = v.y; }
#pragma unroll
    for (int k = 0; k < 7; k++) { float2 v = p2[pb   + k]; prv[2*k] = v.x; prv[2*k+1] = v.y; }
#pragma unroll
    for (int k = 0; k < 7; k++) { float2 v = p2[nb   + k]; nxt[2*k] = v.x; nxt[2*k+1] = v.y; }

    // ---- data loss (COMP_W == 1 everywhere) ----
    float dsq[SD];
#pragma unroll
    for (int k = 0; k < 7; k++) {
        float2 v = t2[base + k];
        float d0 = cur[2*k]   - v.x;
        float d1 = cur[2*k+1] - v.y;
        dsq[2*k] = d0 * d0; dsq[2*k+1] = d1 * d1;
    }
    float s_tr = 0.f, s_rot = 0.f;
#pragma unroll
    for (int k = 0; k < 6; k++)  s_tr  += dsq[k];
#pragma unroll
    for (int k = 6; k < 13; k++) s_rot += dsq[k];
    const float s_ms = dsq[13];

    // ---- finite-difference 1/dt (t is tiny: L1/L2-resident) ----
    float dt;
    if      (n == 0)      dt = t[1]      - t[0];
    else if (n == NN - 1) dt = t[NN - 1] - t[NN - 2];
    else                  dt = t[n + 1]  - t[n - 1];
    const float inv_dt = 1.0f / (dt + 1e-12f);

    // ---- dynamics ----
    const float vx = cur[3], vy = cur[4], vz = cur[5];
    const float q0 = cur[6], q1 = cur[7], q2 = cur[8], q3 = cur[9];
    const float wx = cur[10], wy = cur[11], wz = cur[12];
    const float m  = cur[13];
    const float4 u = reinterpret_cast<const float4*>(ctrl)[i];   // 16B-aligned

    const float thrust = u.x * 1.0e6f;
    const float bz0 = 2.0f * (q1 * q3 + q0 * q2);
    const float bz1 = 2.0f * (q2 * q3 - q0 * q1);
    const float bz2 = 1.0f - 2.0f * (q1 * q1 + q2 * q2);
    const float speed = sqrtf(vx * vx + vy * vy + vz * vz + 1e-12f);
    const float dc    = -0.30625f * speed;     // -0.5 * rho * Cd * A * speed
    const float invm  = 1.0f / m;

    float dyn[SD];
    dyn[0] = vx; dyn[1] = vy; dyn[2] = vz;
    dyn[3] = (thrust * bz0 + dc * vx) * invm;
    dyn[4] = (thrust * bz1 + dc * vy) * invm;
    dyn[5] = (thrust * bz2 + dc * vz) * invm - 9.80665f;
    dyn[6] = 0.5f * (-q1 * wx - q2 * wy - q3 * wz);
    dyn[7] = 0.5f * ( q0 * wx + q2 * wz - q3 * wy);
    dyn[8] = 0.5f * ( q0 * wy - q1 * wz + q3 * wx);
    dyn[9] = 0.5f * ( q0 * wz + q1 * wy - q2 * wx);
    dyn[10] = (u.y * 1.0e4f + 4000.0f * wy * wz) * (1.0f / 5000.0f);  // -(Izz-Iyy)=+4000
    dyn[11] = (u.z * 1.0e4f - 4000.0f * wz * wx) * (1.0f / 5000.0f);  // -(Ixx-Izz)=-4000
    dyn[12] =  u.w * 1.0e4f * (1.0f / 1000.0f);                       // (Iyy-Ixx)=0
    dyn[13] = -thrust * (1.0f / 2941.995f);                           // Isp*g0

    // ---- physics residual (boundary-safe: prv/nxt collapse to cur at ends) ----
    float s_ph = 0.f;
#pragma unroll
    for (int k = 0; k < SD; k++) {
        float r = (nxt[k] - prv[k]) * inv_dt - dyn[k];
        s_ph += r * r;
    }

    // ---- quaternion norm loss ----
    const float qn = sqrtf(q0 * q0 + q1 * q1 + q2 * q2 + q3 * q3);
    const float dq = qn - 1.0f;
    const float s_q = dq * dq;

    // ---- mass-flow loss: relu(mass[n+1]-mass[n]); exactly 0 at n==NN-1 ----
    const float s_mf = fmaxf(nxt[13] - cur[13], 0.0f);

    // ---- block reduction: warp shuffle -> shared -> double partials ----
    __shared__ float wsum[TPB / 32][6];
    {
        float vals[6] = { s_tr, s_rot, s_ms, s_ph, s_q, s_mf };
#pragma unroll
        for (int c = 0; c < 6; c++) {
            float v = vals[c];
#pragma unroll
            for (int o = 16; o > 0; o >>= 1) v += __shfl_down_sync(0xffffffffu, v, o);
            if ((tid & 31) == 0) wsum[tid >> 5][c] = v;
        }
    }
    __syncthreads();
    if (tid < 6) {
        double s = 0.0;
#pragma unroll
        for (int w = 0; w < TPB / 32; w++) s += (double)wsum[w][tid];
        g_part[blockIdx.x * 6 + tid] = s;
    }

    // ---- last-block-done: ticket ----
    __shared__ bool s_last;
    __threadfence();                 // make g_part writes visible before ticket
    __syncthreads();                 // all warps' partial stores issued
    if (tid == 0) {
        unsigned int ticket = atomicAdd(&g_count, 1u);
        s_last = (ticket == NBLK - 1);
    }
    __syncthreads();
    if (!s_last) return;

    // ======================= TAIL (last block only) =======================
    if (tid == 0) g_count = 0;       // reset for next graph replay

    __shared__ double shd[TPB];

    // 1) reduce the 8192 x 6 double partials (bypass L1 for cross-SM data)
    double acc[6] = {0, 0, 0, 0, 0, 0};
    for (int b = tid; b < NBLK; b += TPB) {
        const double* p = &g_part[b * 6];
#pragma unroll
        for (int c = 0; c < 6; c++) acc[c] += __ldcg(p + c);
    }
    double tot[6];
#pragma unroll
    for (int c = 0; c < 6; c++) {
        shd[tid] = acc[c];
        __syncthreads();
        for (int s = TPB / 2; s > 0; s >>= 1) {
            if (tid < s) shd[tid] += shd[tid + s];
            __syncthreads();
        }
        tot[c] = shd[0];
        __syncthreads();
    }

    // 2) argmin_n |t[0,n]| (first index on tie), unrolled for MLP
    __shared__ float sval[TPB];
    __shared__ int   sidx[TPB];
    {
        float best = 3.4e38f;
        int   bidx = 0;
#pragma unroll 4
        for (int b = tid; b < NN; b += TPB) {
            float v = fabsf(t[b]);
            if (v < best) { best = v; bidx = b; }
        }
        sval[tid] = best; sidx[tid] = bidx;
        __syncthreads();
        for (int s = TPB / 2; s > 0; s >>= 1) {
            if (tid < s) {
                float v2 = sval[tid + s]; int i2 = sidx[tid + s];
                if (v2 < sval[tid] || (v2 == sval[tid] && i2 < sidx[tid])) {
                    sval[tid] = v2; sidx[tid] = i2;
                }
            }
            __syncthreads();
        }
    }
    const int tix = sidx[0];
    __syncthreads();

    // 3) BC term: sum over b,k of (pred[b,tix,k]-true[b,tix,k])^2  (L2-hot)
    {
        const int rb = (tid * NN + tix) * 7;    // thread 'tid' handles batch b=tid
        float s_bc = 0.f;
#pragma unroll
        for (int k = 0; k < 7; k++) {
            float2 a = __ldcg(&p2[rb + k]);
            float2 c = __ldcg(&t2[rb + k]);
            float d0 = a.x - c.x, d1 = a.y - c.y;
            s_bc += d0 * d0 + d1 * d1;
        }
        shd[tid] = (double)s_bc;
        __syncthreads();
        for (int s = TPB / 2; s > 0; s >>= 1) {
            if (tid < s) shd[tid] += shd[tid + s];
            __syncthreads();
        }
    }

    // 4) finalize
    if (tid == 0) {
        const double BN = (double)BB * (double)NN;
        double L_data = tot[0] / (BN * 6.0) + tot[1] / (BN * 7.0) + tot[2] / BN;
        double L_phys = tot[3] / (BN * 14.0);
        double L_quat = tot[4] / BN;
        double L_mf   = tot[5] / ((double)BB * (double)(NN - 1));
        double L_bc   = shd[0] / ((double)BB * 14.0);
        double total  = 1.0 * L_data + 0.1 * L_phys + 1.0 * L_bc
                      + 0.01 * L_quat + 0.01 * L_mf;
        out[0] = (float)total;
        out[1] = (float)L_data;
        out[2] = (float)L_phys;
        out[3] = (float)L_bc;
        out[4] = (float)L_quat;
        out[5] = (float)L_mf;
    }
}

// ---------------------------------------------------------------------------
extern "C" void kernel_launch(void* const* d_in, const int* in_sizes, int n_in,
                              void* d_out, int out_size)
{
    const float* pred = (const float*)d_in[0];   // (B, N, 14) f32
    const float* tru  = (const float*)d_in[1];   // (B, N, 14) f32
    const float* t    = (const float*)d_in[2];   // (B, N, 1)  f32 (broadcast over B)
    const float* ctrl = (const float*)d_in[3];   // (B, N, 4)  f32
    float* out        = (float*)d_out;           // 6 f32

    pinn_fused_kernel<<<NBLK, TPB>>>(pred, tru, t, ctrl, out);
}